// round 7
// baseline (speedup 1.0000x reference)
#include <cuda_runtime.h>

#define SC   25     // (LMAX+1)^2
#define RBC  12
#define RAC  11
#define DC   64
#define NP   15     // (l, m>=0) pairs
#define TPB  256
#define RPC  128    // rows per CTA

typedef unsigned long long u64;

// ---------- packed f32x2 helpers ----------
__device__ __forceinline__ u64 pk(float lo, float hi) {
    u64 r; asm("mov.b64 %0, {%1,%2};" : "=l"(r) : "f"(lo), "f"(hi)); return r;
}
__device__ __forceinline__ void unpk(u64 v, float& lo, float& hi) {
    asm("mov.b64 {%0,%1}, %2;" : "=f"(lo), "=f"(hi) : "l"(v));
}
__device__ __forceinline__ u64 fma2(u64 a, u64 b, u64 c) {
    u64 d; asm("fma.rn.f32x2 %0, %1, %2, %3;" : "=l"(d) : "l"(a), "l"(b), "l"(c)); return d;
}
__device__ __forceinline__ u64 add2(u64 a, u64 b) {
    u64 d; asm("add.rn.f32x2 %0, %1, %2;" : "=l"(d) : "l"(a), "l"(b)); return d;
}

// (l,m) pair tables, p = l(l+1)/2 + m, m = 0..l (folded at compile time in unrolled loops)
static __device__ const int c_ip[NP] = {0, 2,3, 6,7,8, 12,13,14,15, 20,21,22,23,24};
static __device__ const int c_in[NP] = {0, 2,1, 6,5,4, 12,11,10, 9, 20,19,18,17,16};
static __device__ const int c_m [NP] = {0, 0,1, 0,1,2,  0, 1, 2, 3,  0, 1, 2, 3, 4};

__global__ void __launch_bounds__(TPB, 2)
gtp_main(const float* __restrict__ x1, const float* __restrict__ x2,
         const float* __restrict__ W1, const float* __restrict__ W2,
         const float* __restrict__ Y,  const float* __restrict__ Yw,
         float* __restrict__ out, int nrows)
{
    // Union region A (29.7KB), re-purposed per phase:
    //  phase 1: A[0..1663] = sW (u64 (W1,W2) pairs, 64 x 26), A[1664..3711] = 1024 float4 staging
    //  phase 2: A[0..3199] = sCs: c pairs (c1,c2) at [s*128 + row]
    //  phase 3: A[0..2047] = sRed (acc exchange), A[2048..3647] = float output staging
    __shared__ __align__(16) u64 A[3712];
    __shared__ __align__(16) u64 sP  [RBC * 16];  // (P,P)
    __shared__ __align__(16) u64 sPw [RBC * 16];  // (P*qw, P*qw)
    __shared__ __align__(16) u64 sAngM[6 * 8];    // (sqrt2 cos, sqrt2 sin); m=0 -> (1,0)
    __shared__ __align__(16) u64 sAngC[6 * 8];    // (cos, cos) dup;         m=0 -> (1,1)
    __shared__ __align__(16) u64 sAngS[6 * 8];    // (sin, sin) dup;         m=0 -> (0,0)

    const int tid = threadIdx.x;
    const int h   = tid >> 7;        // row half: 0 or 1 (uniform per warp)
    const int row = tid & 127;
    const float SQ2  = 1.41421356237309505f;
    const float ISQ2 = 0.70710678118654752f;

    u64* sW = A;
    float4* sBuf = (float4*)(A + DC * 26);

    // ---- build tables from W / Y / Yw (exact extraction, no trig) ----
    for (int k = tid; k < DC * 26; k += TPB) {
        int d = k / 26, s = k % 26;
        sW[k] = (s < SC) ? pk(W1[d * SC + s], W2[d * SC + s]) : 0ull;
    }

    for (int t = tid; t < RBC * 16; t += TPB) {
        int b = t / 16, p = t % 16;
        if (p == 15) { sP[t] = 0ull; sPw[t] = 0ull; }
        else {
            int l = (p >= 10) ? 4 : (p >= 6) ? 3 : (p >= 3) ? 2 : (p >= 1) ? 1 : 0;
            int m = p - l * (l + 1) / 2;
            int ip = l * l + l + m;
            float y0 = Y[(b * RAC) * SC + ip];                 // a=0: ang=1 (m=0) or sqrt2 (m>0)
            float P  = (m > 0) ? y0 * ISQ2 : y0;
            float qw = Yw[(b * RAC) * SC] / Y[(b * RAC) * SC]; // Y[b,0,0] > 0, const over a
            sP [t] = pk(P, P);
            float pw = P * qw;
            sPw[t] = pk(pw, pw);
        }
    }

    // alpha half-grid j=0..5 (points a=6..10 mirror a=5..1)
    for (int t = tid; t < 6 * 5; t += TPB) {
        int j = t / 5, m = t % 5;
        float ac2, as2;
        if (m == 0) { ac2 = 1.0f; as2 = 0.0f; }
        else {
            const int b0 = RBC / 2;                            // mid Gauss node, P[m,m] != 0
            int ip = m * m + 2 * m, in_ = m * m;
            float den = Y[(b0 * RAC) * SC + ip];               // sqrt2 * P[m,m](x_b0)
            ac2 = SQ2 * Y[(b0 * RAC + j) * SC + ip ] / den;
            as2 = SQ2 * Y[(b0 * RAC + j) * SC + in_] / den;
        }
        sAngM[j * 8 + m] = pk(ac2, as2);
        sAngC[j * 8 + m] = pk(ac2, ac2);
        sAngS[j * 8 + m] = pk(as2, as2);
    }
    __syncthreads();

    // ================= phase 1: projection, half of s-range per thread ===========
    // cc[i] = (c1[s0+i], c2[s0+i]) = sum_d (x1[d],x2[d]) * (W1[d,s0+i],W2[d,s0+i])
    const int s0 = h ? 13 : 0;
    const int ns = h ? 12 : 13;
    u64 cc[13];
    #pragma unroll
    for (int i = 0; i < 13; i++) cc[i] = 0ull;

    const long long rowsLeft = (long long)nrows - (long long)blockIdx.x * RPC;
    const long long base = (long long)blockIdx.x * RPC * DC;

    #pragma unroll 1
    for (int q = 0; q < 4; q++) {
        __syncthreads();
        // stage this d-quarter: 128 rows x 16 floats x 2 inputs (256 threads, 2 float4 each/input)
        {
            int rs = tid >> 1, c8 = tid & 1;
            long long rg = (rs < rowsLeft) ? rs : (rowsLeft - 1);
            long long g = base + rg * DC + q * 16 + c8 * 8;
            int c40 = 2 * c8, c41 = 2 * c8 + 1;
            int i0 = c40 * 128 + ((rs + 2 * c40) & 127);
            int i1 = c41 * 128 + ((rs + 2 * c41) & 127);
            sBuf[i0]       = *(const float4*)(x1 + g);
            sBuf[i1]       = *(const float4*)(x1 + g + 4);
            sBuf[512 + i0] = *(const float4*)(x2 + g);
            sBuf[512 + i1] = *(const float4*)(x2 + g + 4);
        }
        __syncthreads();
        #pragma unroll
        for (int j = 0; j < 4; j++) {
            int idx = j * 128 + ((row + 2 * j) & 127);
            float4 A4 = sBuf[idx];
            float4 B4 = sBuf[512 + idx];
            float av[4] = {A4.x, A4.y, A4.z, A4.w};
            float bv[4] = {B4.x, B4.y, B4.z, B4.w};
            #pragma unroll
            for (int w = 0; w < 4; w++) {
                int d = q * 16 + j * 4 + w;
                u64 xd = pk(av[w], bv[w]);               // (x1[d], x2[d])
                const u64* Wd = &sW[d * 26 + s0];
                #pragma unroll
                for (int i = 0; i < 13; i++)             // uniform 13; h=1's 13th hits zero pad
                    cc[i] = fma2(xd, Wd[i], cc[i]);
            }
        }
    }

    // ---- publish c to shared (W + staging dead) ----
    __syncthreads();
    u64* sCs = A;                      // [s*128 + row]
    #pragma unroll
    for (int i = 0; i < 13; i++)
        if (i < ns) sCs[(s0 + i) * 128 + row] = cc[i];
    __syncthreads();

    // ================= phase 2: sphere, 6 beta nodes per thread ==================
    u64 accp[NP];
    #pragma unroll
    for (int p = 0; p < NP; p++) accp[p] = 0ull;

    #pragma unroll 1
    for (int bb = 0; bb < 6; bb++) {
        const int b = h * 6 + bb;
        const u64* Pv  = &sP [b * 16];
        const u64* Pwv = &sPw[b * 16];

        // F[4+m'] = (F1,F2)[m'] = sum_l (c1,c2)[idx(l,m')] * P[l,|m'|]
        u64 F[9];
        #pragma unroll
        for (int i = 0; i < 9; i++) F[i] = 0ull;
        #pragma unroll
        for (int p = 0; p < NP; p++) {
            u64 P = Pv[p];
            u64 cip = sCs[c_ip[p] * 128 + row];
            F[4 + c_m[p]] = fma2(cip, P, F[4 + c_m[p]]);
            if (c_m[p] > 0) {
                u64 cin = sCs[c_in[p] * 128 + row];
                F[4 - c_m[p]] = fma2(cin, P, F[4 - c_m[p]]);
            }
        }

        u64 H[5];
        #pragma unroll
        for (int m = 0; m < 5; m++) H[m] = 0ull;

        // j = 0 (self-mirror, sin terms vanish)
        {
            u64 E = 0ull;
            #pragma unroll
            for (int m = 0; m < 5; m++) E = fma2(F[4 + m], sAngC[m], E);
            float e1, e2; unpk(E, e1, e2);
            float ha = e1 * e2;
            u64 hp = pk(ha, ha);
            #pragma unroll
            for (int m = 0; m < 5; m++) H[m] = fma2(hp, sAngM[m], H[m]);
        }
        // j = 1..5: mirror pairs (a=j, a=11-j) via even/odd split
        #pragma unroll
        for (int j = 1; j < 6; j++) {
            u64 E = 0ull, O = 0ull;
            #pragma unroll
            for (int m = 0; m < 5; m++) E = fma2(F[4 + m], sAngC[j * 8 + m], E);
            #pragma unroll
            for (int m = 1; m < 5; m++) O = fma2(F[4 - m], sAngS[j * 8 + m], O);
            float e1, e2, o1, o2;
            unpk(E, e1, e2); unpk(O, o1, o2);
            float ha = (e1 + o1) * (e2 + o2);      // grid product at a = j
            float hb = (e1 - o1) * (e2 - o2);      // grid product at a = 11 - j
            u64 hp = pk(ha + hb, ha - hb);         // (cos lane, sin lane)
            #pragma unroll
            for (int m = 0; m < 5; m++) H[m] = fma2(hp, sAngM[j * 8 + m], H[m]);
        }

        #pragma unroll
        for (int p = 0; p < NP; p++)
            accp[p] = fma2(H[c_m[p]], Pwv[p], accp[p]);
    }

    // ================= phase 3: cross-half reduction + coalesced output ==========
    __syncthreads();                   // all reads of sCs done
    u64* sRed = A;                     // [row*16 + swizzled p]
    if (h == 1) {
        #pragma unroll
        for (int p = 0; p < NP; p++)
            sRed[row * 16 + ((p + row) & 15)] = accp[p];
    }
    __syncthreads();
    float* sOutF = (float*)(A + 2048);
    if (h == 0) {
        #pragma unroll
        for (int p = 0; p < NP; p++) {
            u64 t = add2(accp[p], sRed[row * 16 + ((p + row) & 15)]);
            float lo, hi; unpk(t, lo, hi);
            sOutF[row * SC + c_ip[p]] = lo;
            if (c_m[p] > 0) sOutF[row * SC + c_in[p]] = hi;
        }
    }
    __syncthreads();
    const float4* sOv = (const float4*)sOutF;
    const long long obase4 = (long long)blockIdx.x * RPC * SC / 4;   // 800 float4 per CTA
    const long long otot4  = (long long)nrows * SC / 4;
    float4* og = (float4*)out;
    #pragma unroll
    for (int k = tid; k < RPC * SC / 4; k += TPB) {
        if (obase4 + k < otot4) og[obase4 + k] = sOv[k];
    }
}

extern "C" void kernel_launch(void* const* d_in, const int* in_sizes, int n_in,
                              void* d_out, int out_size) {
    const float* x1 = (const float*)d_in[0];
    const float* x2 = (const float*)d_in[1];
    const float* W1 = (const float*)d_in[2];
    const float* W2 = (const float*)d_in[3];
    const float* Y  = (const float*)d_in[4];
    const float* Yw = (const float*)d_in[5];
    float* out = (float*)d_out;

    const int nrows = in_sizes[0] / DC;            // 131072
    const int grid  = (nrows + RPC - 1) / RPC;     // 1024

    gtp_main<<<grid, TPB>>>(x1, x2, W1, W2, Y, Yw, out, nrows);
}

// round 8
// speedup vs baseline: 1.2659x; 1.2659x over previous
#include <cuda_runtime.h>

#define SC   25     // (LMAX+1)^2
#define RBC  12
#define RAC  11
#define DC   64
#define NP   15     // (l, m>=0) pairs
#define TPB  128
#define MAXT 1024   // max tiles (131072/128)

typedef unsigned long long u64;

// scratch: [tile][s(25)][row(128)] u64 pairs (c1[s], c2[s])
__device__ u64 g_scr[MAXT * SC * TPB];

// ---------- packed f32x2 helpers ----------
__device__ __forceinline__ u64 pk(float lo, float hi) {
    u64 r; asm("mov.b64 %0, {%1,%2};" : "=l"(r) : "f"(lo), "f"(hi)); return r;
}
__device__ __forceinline__ void unpk(u64 v, float& lo, float& hi) {
    asm("mov.b64 {%0,%1}, %2;" : "=f"(lo), "=f"(hi) : "l"(v));
}
__device__ __forceinline__ u64 fma2(u64 a, u64 b, u64 c) {
    u64 d; asm("fma.rn.f32x2 %0, %1, %2, %3;" : "=l"(d) : "l"(a), "l"(b), "l"(c)); return d;
}

// (l,m) pair tables, p = l(l+1)/2 + m, m = 0..l (fold at compile time in unrolled loops)
static __device__ const int c_ip[NP] = {0, 2,3, 6,7,8, 12,13,14,15, 20,21,22,23,24};
static __device__ const int c_in[NP] = {0, 2,1, 6,5,4, 12,11,10, 9, 20,19,18,17,16};
static __device__ const int c_m [NP] = {0, 0,1, 0,1,2,  0, 1, 2, 3,  0, 1, 2, 3, 4};

// ======================= kernel A: projection =======================
__global__ void __launch_bounds__(TPB, 5)
gtp_proj(const float* __restrict__ x1, const float* __restrict__ x2,
         const float* __restrict__ W1, const float* __restrict__ W2,
         int nrows)
{
    __shared__ __align__(16) u64 sW[DC * 26];     // (W1[d,s], W2[d,s]) pairs; 13.3KB
    __shared__ __align__(16) float4 sBuf[1024];   // input staging; 16KB

    const int tid = threadIdx.x;

    for (int k = tid; k < DC * 26; k += TPB) {
        int d = k / 26, s = k % 26;
        sW[k] = (s < SC) ? pk(W1[d * SC + s], W2[d * SC + s]) : 0ull;
    }

    u64 cc[SC];
    #pragma unroll
    for (int s = 0; s < SC; s++) cc[s] = 0ull;

    const long long rowsLeft = (long long)nrows - (long long)blockIdx.x * TPB;
    const long long base = (long long)blockIdx.x * TPB * DC;

    #pragma unroll 1
    for (int q = 0; q < 4; q++) {
        __syncthreads();
        #pragma unroll
        for (int i = 0; i < 4; i++) {
            int k = i * TPB + tid;            // 0..511
            int row = k >> 2, c4 = k & 3;
            long long rg = (row < rowsLeft) ? row : (rowsLeft - 1);
            long long g = base + rg * DC + q * 16 + c4 * 4;
            int idx = c4 * 128 + ((row + 2 * c4) & 127);   // conflict-free STS/LDS
            sBuf[idx]       = *(const float4*)(x1 + g);
            sBuf[512 + idx] = *(const float4*)(x2 + g);
        }
        __syncthreads();
        #pragma unroll
        for (int j = 0; j < 4; j++) {
            int idx = j * 128 + ((tid + 2 * j) & 127);
            float4 A4 = sBuf[idx];
            float4 B4 = sBuf[512 + idx];
            float av[4] = {A4.x, A4.y, A4.z, A4.w};
            float bv[4] = {B4.x, B4.y, B4.z, B4.w};
            #pragma unroll
            for (int w = 0; w < 4; w++) {
                int d = q * 16 + j * 4 + w;
                u64 xd = pk(av[w], bv[w]);               // (x1[d], x2[d])
                const u64* Wd = &sW[d * 26];
                #pragma unroll
                for (int s = 0; s < SC; s++)
                    cc[s] = fma2(xd, Wd[s], cc[s]);
            }
        }
    }

    // coalesced scratch write: [tile][s][row]
    u64* dst = g_scr + (long long)blockIdx.x * (SC * TPB) + tid;
    #pragma unroll
    for (int s = 0; s < SC; s++) dst[s * TPB] = cc[s];
}

// ======================= kernel B: sphere =======================
__global__ void __launch_bounds__(TPB, 4)
gtp_sphere(const float* __restrict__ Y, const float* __restrict__ Yw,
           float* __restrict__ out, int nrows)
{
    __shared__ __align__(16) u64 sP  [RBC * 16];   // (P,P)
    __shared__ __align__(16) u64 sPw [RBC * 16];   // (P*qw, P*qw)
    __shared__ __align__(16) u64 sAngJ[6 * 16];    // per mirror-point j: C0..C4,S1..S4,M0..M4
    __shared__ __align__(16) float sOutF[TPB * SC]; // output staging; 12.8KB

    const int tid = threadIdx.x;
    const float SQ2  = 1.41421356237309505f;
    const float ISQ2 = 0.70710678118654752f;

    for (int t = tid; t < RBC * 16; t += TPB) {
        int b = t / 16, p = t % 16;
        if (p == 15) { sP[t] = 0ull; sPw[t] = 0ull; }
        else {
            int l = (p >= 10) ? 4 : (p >= 6) ? 3 : (p >= 3) ? 2 : (p >= 1) ? 1 : 0;
            int m = p - l * (l + 1) / 2;
            int ip = l * l + l + m;
            float y0 = Y[(b * RAC) * SC + ip];                 // a=0: ang=1 (m=0) or sqrt2 (m>0)
            float P  = (m > 0) ? y0 * ISQ2 : y0;
            float qw = Yw[(b * RAC) * SC] / Y[(b * RAC) * SC]; // Y[b,0,0] > 0, const over a
            sP [t] = pk(P, P);
            float pw = P * qw;
            sPw[t] = pk(pw, pw);
        }
    }

    // angle table per half-grid point j (a=6..10 mirror a=5..1):
    // slots [0..4]=(c_m,c_m), [5..8]=(s_m,s_m) m=1..4, [9..13]=(c_m,s_m), [14..15]=pad
    for (int t = tid; t < 6 * 16; t += TPB) {
        int j = t / 16, k = t % 16;
        if (k >= 14) { sAngJ[t] = 0ull; continue; }
        int m = (k <= 4) ? k : (k <= 8) ? (k - 4) : (k - 9);
        float cm, sm;
        if (m == 0) { cm = 1.0f; sm = 0.0f; }
        else {
            const int b0 = RBC / 2;                            // mid Gauss node, P[m,m] != 0
            int ip = m * m + 2 * m, in_ = m * m;
            float den = Y[(b0 * RAC) * SC + ip];               // sqrt2 * P[m,m](x_b0)
            cm = SQ2 * Y[(b0 * RAC + j) * SC + ip ] / den;
            sm = SQ2 * Y[(b0 * RAC + j) * SC + in_] / den;
        }
        sAngJ[t] = (k <= 4) ? pk(cm, cm) : (k <= 8) ? pk(sm, sm) : pk(cm, sm);
    }
    __syncthreads();

    // load projected coefficients (c1,c2)-packed, coalesced
    const u64* src = g_scr + (long long)blockIdx.x * (SC * TPB) + tid;
    u64 cc[SC];
    #pragma unroll
    for (int s = 0; s < SC; s++) cc[s] = src[s * TPB];

    u64 accp[NP];
    #pragma unroll
    for (int p = 0; p < NP; p++) accp[p] = 0ull;

    #pragma unroll 1
    for (int b = 0; b < RBC; b++) {
        const ulonglong2* Pv  = (const ulonglong2*)&sP [b * 16];
        const ulonglong2* Pwv = (const ulonglong2*)&sPw[b * 16];

        // F[4+m'] = (F1[m'],F2[m']) = sum_l cc[idx(l,m')] * P[l,|m'|]
        u64 F[9];
        #pragma unroll
        for (int i = 0; i < 9; i++) F[i] = 0ull;
        #pragma unroll
        for (int pp = 0; pp < 8; pp++) {
            ulonglong2 P2 = Pv[pp];
            const int p0 = 2 * pp, p1 = 2 * pp + 1;
            F[4 + c_m[p0]] = fma2(cc[c_ip[p0]], P2.x, F[4 + c_m[p0]]);
            if (c_m[p0] > 0) F[4 - c_m[p0]] = fma2(cc[c_in[p0]], P2.x, F[4 - c_m[p0]]);
            if (p1 < NP) {
                F[4 + c_m[p1]] = fma2(cc[c_ip[p1]], P2.y, F[4 + c_m[p1]]);
                if (c_m[p1] > 0) F[4 - c_m[p1]] = fma2(cc[c_in[p1]], P2.y, F[4 - c_m[p1]]);
            }
        }

        u64 H[5];   // H[m] = (H+_m, H-_m)
        #pragma unroll
        for (int m = 0; m < 5; m++) H[m] = 0ull;

        #pragma unroll
        for (int j = 0; j < 6; j++) {
            const ulonglong2* Aj = (const ulonglong2*)&sAngJ[j * 16];
            ulonglong2 e0 = Aj[0], e1 = Aj[1], e2 = Aj[2], e3 = Aj[3],
                       e4 = Aj[4], e5 = Aj[5], e6 = Aj[6];
            u64 C0 = e0.x, C1 = e0.y, C2 = e1.x, C3 = e1.y, C4 = e2.x;
            u64 S1 = e2.y, S2 = e3.x, S3 = e3.y, S4 = e4.x;
            u64 M0 = e4.y, M1 = e5.x, M2 = e5.y, M3 = e6.x, M4 = e6.y;

            // even part: (E1,E2) = sum_{m>=0} F[4+m]*c_m ; odd: (O1,O2) = sum_{m>0} F[4-m]*s_m
            u64 E = 0ull;
            E = fma2(F[4], C0, E);
            E = fma2(F[5], C1, E);
            E = fma2(F[6], C2, E);
            E = fma2(F[7], C3, E);
            E = fma2(F[8], C4, E);

            u64 hp;
            if (j == 0) {                          // a = 0: self-mirror, odd part = 0
                float e1f, e2f; unpk(E, e1f, e2f);
                float ha = e1f * e2f;
                hp = pk(ha, ha);
            } else {
                u64 O = 0ull;
                O = fma2(F[3], S1, O);
                O = fma2(F[2], S2, O);
                O = fma2(F[1], S3, O);
                O = fma2(F[0], S4, O);
                float e1f, e2f, o1f, o2f;
                unpk(E, e1f, e2f); unpk(O, o1f, o2f);
                float ha = (e1f + o1f) * (e2f + o2f);   // grid product at a = j
                float hb = (e1f - o1f) * (e2f - o2f);   // grid product at a = 11 - j
                hp = pk(ha + hb, ha - hb);
            }
            // H[m] += hp * (c_m, s_m)
            H[0] = fma2(hp, M0, H[0]);
            H[1] = fma2(hp, M1, H[1]);
            H[2] = fma2(hp, M2, H[2]);
            H[3] = fma2(hp, M3, H[3]);
            H[4] = fma2(hp, M4, H[4]);
        }

        #pragma unroll
        for (int pp = 0; pp < 8; pp++) {
            ulonglong2 Pw2 = Pwv[pp];
            const int p0 = 2 * pp, p1 = 2 * pp + 1;
            accp[p0] = fma2(H[c_m[p0]], Pw2.x, accp[p0]);
            if (p1 < NP) accp[p1] = fma2(H[c_m[p1]], Pw2.y, accp[p1]);
        }
    }

    // output via shared staging, coalesced float4 stores
    #pragma unroll
    for (int p = 0; p < NP; p++) {
        float lo, hi; unpk(accp[p], lo, hi);
        sOutF[tid * SC + c_ip[p]] = lo;
        if (c_m[p] > 0) sOutF[tid * SC + c_in[p]] = hi;
    }
    __syncthreads();
    const float4* sOv = (const float4*)sOutF;
    const long long obase4 = (long long)blockIdx.x * TPB * SC / 4;   // 800 float4 per CTA
    const long long otot4  = (long long)nrows * SC / 4;
    float4* og = (float4*)out;
    #pragma unroll
    for (int k = tid; k < TPB * SC / 4; k += TPB) {
        if (obase4 + k < otot4) og[obase4 + k] = sOv[k];
    }
}

extern "C" void kernel_launch(void* const* d_in, const int* in_sizes, int n_in,
                              void* d_out, int out_size) {
    const float* x1 = (const float*)d_in[0];
    const float* x2 = (const float*)d_in[1];
    const float* W1 = (const float*)d_in[2];
    const float* W2 = (const float*)d_in[3];
    const float* Y  = (const float*)d_in[4];
    const float* Yw = (const float*)d_in[5];
    float* out = (float*)d_out;

    const int nrows = in_sizes[0] / DC;            // 131072
    int grid = (nrows + TPB - 1) / TPB;            // 1024
    if (grid > MAXT) grid = MAXT;

    gtp_proj  <<<grid, TPB>>>(x1, x2, W1, W2, nrows);
    gtp_sphere<<<grid, TPB>>>(Y, Yw, out, nrows);
}